// round 16
// baseline (speedup 1.0000x reference)
#include <cuda_runtime.h>
#include <math.h>

#define DIMX 512
#define CBD  14
#define CBS  16384
#define NTHR 256
#define TPB  32           // tokens per block-group
#define MAXBLK 128
#define FINBLK 64

typedef unsigned long long ull;

// Persistent device scratch (zero-initialized at load; lfq_final re-zeros after use)
__device__ float g_avgp[CBS];
__device__ float g_scal[2];          // [0] entropy sum, [1] commit sum
__device__ float g_ent;              // codebook-entropy accumulator
__device__ unsigned int g_ctr;       // final-kernel arrival counter

// ---- packed f32x2 helpers ----
__device__ __forceinline__ ull ffma2(ull a, ull b, ull c) {
    ull d; asm("fma.rn.f32x2 %0, %1, %2, %3;" : "=l"(d) : "l"(a), "l"(b), "l"(c)); return d;
}
__device__ __forceinline__ ull fadd2(ull a, ull b) {
    ull d; asm("add.rn.f32x2 %0, %1, %2;" : "=l"(d) : "l"(a), "l"(b)); return d;
}
__device__ __forceinline__ ull pack2(float lo, float hi) {
    ull r; asm("mov.b64 %0, {%1, %2};" : "=l"(r) : "f"(lo), "f"(hi)); return r;
}
__device__ __forceinline__ void unpack2(ull v, float& lo, float& hi) {
    asm("mov.b64 {%0, %1}, %2;" : "=f"(lo), "=f"(hi) : "l"(v));
}

// shared-memory layout (bytes)
#define O_X 0                 // 32 rows x 129 ull2 = 66048
#define O_W 66048             // w_in staged: 14*128 ull2 = 28672
#define O_P 94720             // partials: 8*14*32 ull = 28672
#define O_H 123392            // h: 448 floats = 1792
#define O_Q 125184            // q(+-1): 448 floats = 1792
#define SMEM_TOTAL 126976

__global__ void __launch_bounds__(NTHR, 1) lfq_main(
    const float* __restrict__ x,
    const float* __restrict__ w_in,
    const float* __restrict__ b_in,
    const float* __restrict__ w_out,
    const float* __restrict__ b_out,
    float* __restrict__ out,
    float* __restrict__ idxf,
    int ntok)
{
    extern __shared__ unsigned char smem[];
    ulonglong2* sx  = (ulonglong2*)(smem + O_X);
    ulonglong2* swi = (ulonglong2*)(smem + O_W);
    ull*        sp  = (ull*)       (smem + O_P);
    float*      shh = (float*)     (smem + O_H);
    float*      shq = (float*)     (smem + O_Q);

    const int tid  = threadIdx.x;
    const int lane = tid & 31;
    const int wid  = tid >> 5;

    // ---- prefetch phase-2 weights + biases into registers at kernel top ----
    // (latency overlaps the staging below; removes post-barrier LDG waits)
    float wo0[CBD], wo1[CBD];
#pragma unroll
    for (int d = 0; d < CBD; d++) {
        wo0[d] = __ldg(w_out + tid * CBD + d);
        wo1[d] = __ldg(w_out + (tid + 256) * CBD + d);
    }
    const float bo0 = __ldg(b_out + tid);
    const float bo1 = __ldg(b_out + tid + 256);
    const float bi0 = __ldg(b_in + (tid >> 5));                     // for p = tid (<448)
    const float bi1 = (tid + 256 < 448) ? __ldg(b_in + ((tid + 256) >> 5)) : 0.0f;

    // stage w_in [14][512] into shared once (coalesced, 28KB)
    {
        const ulonglong2* wsrc = (const ulonglong2*)w_in;
#pragma unroll
        for (int i = 0; i < 7; i++) swi[i * 256 + tid] = wsrc[i * 256 + tid];
    }

    for (int base = blockIdx.x * TPB; base < ntok; base += gridDim.x * TPB) {
        __syncthreads();

        // ---- stage 32 token rows of x into padded shared (coalesced) ----
#pragma unroll
        for (int i = 0; i < 16; i++) {
            int idx = i * 256 + tid;
            int t = idx >> 7, c = idx & 127;
            ulonglong2 v;
            if (base + t < ntok) v = *(const ulonglong2*)(x + (size_t)(base + t) * DIMX + c * 4);
            else { v.x = 0ull; v.y = 0ull; }
            sx[t * 129 + c] = v;
        }
        __syncthreads();

        // ---- phase 1: h = x @ w_in^T  (lane = token, warp = 64-col chunk) ----
        ull acc[CBD];
#pragma unroll
        for (int d = 0; d < CBD; d++) acc[d] = 0ull;
        {
            const ulonglong2* xs = sx + lane * 129 + wid * 16;
            const ulonglong2* ws = swi + wid * 16;
#pragma unroll 4
            for (int j = 0; j < 16; j++) {
                ulonglong2 xv = xs[j];
#pragma unroll
                for (int d = 0; d < CBD; d++) {
                    ulonglong2 wv = ws[d * 128 + j];
                    acc[d] = ffma2(xv.x, wv.x, ffma2(xv.y, wv.y, acc[d]));
                }
            }
        }
#pragma unroll
        for (int d = 0; d < CBD; d++) sp[wid * 448 + d * 32 + lane] = acc[d];
        __syncthreads();

        // ---- cross-warp reduce (tree, packed), add b_in (prefetched), sign ----
#pragma unroll
        for (int r = 0; r < 2; r++) {
            int p = tid + r * 256;
            if (p < 448) {
                ull s0 = fadd2(sp[0 * 448 + p], sp[1 * 448 + p]);
                ull s1 = fadd2(sp[2 * 448 + p], sp[3 * 448 + p]);
                ull s2 = fadd2(sp[4 * 448 + p], sp[5 * 448 + p]);
                ull s3 = fadd2(sp[6 * 448 + p], sp[7 * 448 + p]);
                ull s  = fadd2(fadd2(s0, s1), fadd2(s2, s3));
                float lo, hi; unpack2(s, lo, hi);
                float h = lo + hi + (r == 0 ? bi0 : bi1);
                shh[p] = h;
                shq[p] = (h > 0.0f) ? 1.0f : -1.0f;
            }
        }
        __syncthreads();

        // ---- phase 2: out = q @ w_out^T  (two passes, prefetched weights) ----
#pragma unroll 1
        for (int pass = 0; pass < 2; pass++) {
            int e = tid + pass * 256;
            ull a2[16];
            ull binit = pack2(pass == 0 ? bo0 : bo1, pass == 0 ? bo0 : bo1);
#pragma unroll
            for (int tp = 0; tp < 16; tp++) a2[tp] = binit;
#pragma unroll
            for (int d = 0; d < CBD; d++) {
                float w = (pass == 0) ? wo0[d] : wo1[d];
                ull wsp = pack2(w, w);
                const ull* qrow = (const ull*)(shq + d * 32);    // broadcast reads
#pragma unroll
                for (int tp = 0; tp < 16; tp++)
                    a2[tp] = ffma2(qrow[tp], wsp, a2[tp]);
            }
#pragma unroll
            for (int tp = 0; tp < 16; tp++) {
                float lo, hi; unpack2(a2[tp], lo, hi);
                int t0 = base + 2 * tp;
                // streaming stores: keep L2 free for g_avgp atomics
                if (t0 < ntok)     __stcs(out + (size_t)t0 * DIMX + e, lo);
                if (t0 + 1 < ntok) __stcs(out + (size_t)(t0 + 1) * DIMX + e, hi);
            }
        }

        // ---- entropy / index / commit: warp 0, lane = token ----
        if (wid == 0) {
            int t = base + lane;
            float E = 0.0f, commit = 0.0f, lpmax = 0.0f;
            int idx = 0, k = 0;
            float wts[CBD]; int msk[CBD];
            if (t < ntok) {
#pragma unroll
                for (int d = 0; d < CBD; d++) {
                    float hv = shh[d * 32 + lane];
                    float a = fabsf(hv);
                    if (hv > 0.0f) idx |= 1 << (13 - d);
                    float dm = a - 1.0f;
                    commit += dm * dm;
                    float e4 = 400.0f * a;
                    if (e4 < 40.0f) { lpmax -= log1pf(__expf(-e4)); wts[k] = e4; msk[k] = 1 << (13 - d); k++; }
                }
                const float LCLIP = -11.512925465f;   // log(1e-5)
                const int M = 1 << k;
                for (int m = 0; m < M; m++) {
                    float lp = lpmax; int flip = 0;
                    for (int i = 0; i < k; i++)
                        if ((m >> i) & 1) { lp -= wts[i]; flip |= msk[i]; }
                    float p = __expf(lp);
                    E -= p * fmaxf(lp, LCLIP);
                    atomicAdd(&g_avgp[idx ^ flip], p);
                }
                idxf[t] = (float)idx;
            }
#pragma unroll
            for (int o = 16; o; o >>= 1) {
                E      += __shfl_xor_sync(0xffffffffu, E, o);
                commit += __shfl_xor_sync(0xffffffffu, commit, o);
            }
            if (lane == 0) { atomicAdd(&g_scal[0], E); atomicAdd(&g_scal[1], commit); }
        }
    }
}

// grid=FINBLK x 256: one bin per thread; last-arriving block finishes scalar math.
__global__ void __launch_bounds__(256) lfq_final(float* __restrict__ aux, int ntok)
{
    __shared__ float red[8];
    __shared__ bool amlast;
    const int tid = threadIdx.x;
    const int j = blockIdx.x * 256 + tid;       // FINBLK*256 == CBS
    const float inv_n = 1.0f / (float)ntok;

    // prefetch scalar sums off the critical path (written by previous kernel;
    // visible at the launch boundary — no fence needed)
    float ps_sum = 0.0f, cm_sum = 0.0f;
    if (tid == 0) { ps_sum = __ldcg(&g_scal[0]); cm_sum = __ldcg(&g_scal[1]); }

    float v = __ldcg(&g_avgp[j]);
    g_avgp[j] = 0.0f;                           // reset for next graph replay
    float a = v * inv_n;
    float s = -a * __logf(fmaxf(a, 1e-5f));     // a==0 contributes exactly 0

#pragma unroll
    for (int o = 16; o; o >>= 1) s += __shfl_xor_sync(0xffffffffu, s, o);
    if ((tid & 31) == 0) red[tid >> 5] = s;
    __syncthreads();
    if (tid == 0) {
        float bs = red[0];
#pragma unroll
        for (int w = 1; w < 8; w++) bs += red[w];
        atomicAdd(&g_ent, bs);
        __threadfence();                        // release: ent-add before ctr-add
        unsigned int old = atomicAdd(&g_ctr, 1u);
        amlast = (old == (unsigned)(gridDim.x - 1));
    }
    __syncthreads();
    if (amlast && tid == 0) {
        __threadfence();                        // acquire: ctr observation before g_ent read
        float cbent = *(volatile float*)&g_ent;
        float ps = ps_sum * inv_n;
        float cm = cm_sum * (inv_n / (float)CBD);
        aux[0] = 0.1f * (ps - cbent) + 0.25f * cm;
        // reset persistent state for next replay
        g_ent = 0.0f; g_ctr = 0u; g_scal[0] = 0.0f; g_scal[1] = 0.0f;
    }
}

extern "C" void kernel_launch(void* const* d_in, const int* in_sizes, int n_in,
                              void* d_out, int out_size)
{
    const float* x     = (const float*)d_in[0];
    const float* w_in  = (const float*)d_in[1];
    const float* b_in  = (const float*)d_in[2];
    const float* w_out = (const float*)d_in[3];
    const float* b_out = (const float*)d_in[4];

    const int ntok = in_sizes[0] / DIMX;   // 4096

    float* out  = (float*)d_out;
    float* idxf = out + (size_t)ntok * DIMX;
    float* aux  = idxf + ntok;

    cudaFuncSetAttribute(lfq_main, cudaFuncAttributeMaxDynamicSharedMemorySize, SMEM_TOTAL);

    int nblk = (ntok + TPB - 1) / TPB;
    if (nblk > MAXBLK) nblk = MAXBLK;
    lfq_main<<<nblk, NTHR, SMEM_TOTAL>>>(x, w_in, b_in, w_out, b_out, out, idxf, ntok);
    lfq_final<<<FINBLK, 256>>>(aux, ntok);
}

// round 17
// speedup vs baseline: 1.0128x; 1.0128x over previous
#include <cuda_runtime.h>
#include <math.h>

#define DIMX 512
#define CBD  14
#define CBS  16384
#define NTHR 512
#define TPB  32           // tokens per block-group
#define MAXBLK 128
#define FINBLK 64

typedef unsigned long long ull;

// Persistent device scratch (zero-initialized at load; lfq_final re-zeros after use)
__device__ float g_avgp[CBS];
__device__ float g_scal[2];          // [0] entropy sum, [1] commit sum
__device__ float g_ent;              // codebook-entropy accumulator
__device__ unsigned int g_ctr;       // final-kernel arrival counter

// ---- packed f32x2 helpers ----
__device__ __forceinline__ ull ffma2(ull a, ull b, ull c) {
    ull d; asm("fma.rn.f32x2 %0, %1, %2, %3;" : "=l"(d) : "l"(a), "l"(b), "l"(c)); return d;
}
__device__ __forceinline__ ull pack2(float lo, float hi) {
    ull r; asm("mov.b64 %0, {%1, %2};" : "=l"(r) : "f"(lo), "f"(hi)); return r;
}
__device__ __forceinline__ void unpack2(ull v, float& lo, float& hi) {
    asm("mov.b64 {%0, %1}, %2;" : "=f"(lo), "=f"(hi) : "l"(v));
}

// shared-memory layout (bytes)
#define O_X 0                 // 32 rows x 129 ull2 = 66048
#define O_W 66048             // w_in staged: 14*128 ull2 = 28672
#define O_P 94720             // partials (floats): 16*448 = 28672
#define O_H 123392            // h: 448 floats = 1792
#define O_Q 125184            // q(+-1): 448 floats = 1792
#define SMEM_TOTAL 126976

__global__ void __launch_bounds__(NTHR, 1) lfq_main(
    const float* __restrict__ x,
    const float* __restrict__ w_in,
    const float* __restrict__ b_in,
    const float* __restrict__ w_out,
    const float* __restrict__ b_out,
    float* __restrict__ out,
    float* __restrict__ idxf,
    int ntok)
{
    extern __shared__ unsigned char smem[];
    ulonglong2* sx  = (ulonglong2*)(smem + O_X);
    ulonglong2* swi = (ulonglong2*)(smem + O_W);
    float*      spf = (float*)     (smem + O_P);
    float*      shh = (float*)     (smem + O_H);
    float*      shq = (float*)     (smem + O_Q);

    const int tid  = threadIdx.x;
    const int lane = tid & 31;
    const int wid  = tid >> 5;     // 0..15: 32-column chunk

    // ---- prefetch phase-2 weights + biases (latency overlaps staging) ----
    float wo[CBD];
#pragma unroll
    for (int d = 0; d < CBD; d++) wo[d] = __ldg(w_out + tid * CBD + d);
    const float bo = __ldg(b_out + tid);
    const float bi = (tid < 448) ? __ldg(b_in + (tid >> 5)) : 0.0f;

    // stage w_in [14][512] into shared once (coalesced, 28KB; 1792 ull2)
    {
        const ulonglong2* wsrc = (const ulonglong2*)w_in;
#pragma unroll
        for (int i = 0; i < 4; i++) {
            int idx = i * 512 + tid;
            if (idx < 1792) swi[idx] = wsrc[idx];
        }
    }

    for (int base = blockIdx.x * TPB; base < ntok; base += gridDim.x * TPB) {
        __syncthreads();

        // ---- stage 32 token rows of x into padded shared (coalesced) ----
#pragma unroll
        for (int i = 0; i < 8; i++) {
            int idx = i * 512 + tid;             // 0..4095
            int t = idx >> 7, c = idx & 127;
            ulonglong2 v;
            if (base + t < ntok) v = *(const ulonglong2*)(x + (size_t)(base + t) * DIMX + c * 4);
            else { v.x = 0ull; v.y = 0ull; }
            sx[t * 129 + c] = v;
        }
        __syncthreads();

        // ---- phase 1: h = x @ w_in^T  (lane = token, warp = 32-col chunk) ----
        ull acc[CBD];
#pragma unroll
        for (int d = 0; d < CBD; d++) acc[d] = 0ull;
        {
            const ulonglong2* xs = sx + lane * 129 + wid * 8;
            const ulonglong2* ws = swi + wid * 8;
#pragma unroll
            for (int j = 0; j < 8; j++) {
                ulonglong2 xv = xs[j];
#pragma unroll
                for (int d = 0; d < CBD; d++) {
                    ulonglong2 wv = ws[d * 128 + j];
                    acc[d] = ffma2(xv.x, wv.x, ffma2(xv.y, wv.y, acc[d]));
                }
            }
        }
        // store pre-summed float partials (16 warps x 448)
#pragma unroll
        for (int d = 0; d < CBD; d++) {
            float lo, hi; unpack2(acc[d], lo, hi);
            spf[wid * 448 + d * 32 + lane] = lo + hi;
        }
        __syncthreads();

        // ---- cross-warp reduce (tree over 16 partials), add b_in, sign ----
        if (tid < 448) {
            float s = 0.0f;
            float t0 = 0.0f, t1 = 0.0f, t2 = 0.0f, t3 = 0.0f;
#pragma unroll
            for (int w = 0; w < 4; w++) {
                t0 += spf[(4 * w + 0) * 448 + tid];
                t1 += spf[(4 * w + 1) * 448 + tid];
                t2 += spf[(4 * w + 2) * 448 + tid];
                t3 += spf[(4 * w + 3) * 448 + tid];
            }
            s = (t0 + t1) + (t2 + t3);
            float h = s + bi;
            shh[tid] = h;
            shq[tid] = (h > 0.0f) ? 1.0f : -1.0f;
        }
        __syncthreads();

        // ---- phase 2: out = q @ w_out^T  (single pass, e = tid) ----
        {
            ull a2[16];
            ull binit = pack2(bo, bo);
#pragma unroll
            for (int tp = 0; tp < 16; tp++) a2[tp] = binit;
#pragma unroll
            for (int d = 0; d < CBD; d++) {
                ull wsp = pack2(wo[d], wo[d]);
                const ull* qrow = (const ull*)(shq + d * 32);    // broadcast reads
#pragma unroll
                for (int tp = 0; tp < 16; tp++)
                    a2[tp] = ffma2(qrow[tp], wsp, a2[tp]);
            }
#pragma unroll
            for (int tp = 0; tp < 16; tp++) {
                float lo, hi; unpack2(a2[tp], lo, hi);
                int t0 = base + 2 * tp;
                if (t0 < ntok)     __stcs(out + (size_t)t0 * DIMX + tid, lo);   // coalesced over tid
                if (t0 + 1 < ntok) __stcs(out + (size_t)(t0 + 1) * DIMX + tid, hi);
            }
        }

        // ---- entropy / index / commit: warp 0, lane = token ----
        if (wid == 0) {
            int t = base + lane;
            float E = 0.0f, commit = 0.0f, lpmax = 0.0f;
            int idx = 0, k = 0;
            float wts[CBD]; int msk[CBD];
            if (t < ntok) {
#pragma unroll
                for (int d = 0; d < CBD; d++) {
                    float hv = shh[d * 32 + lane];
                    float a = fabsf(hv);
                    if (hv > 0.0f) idx |= 1 << (13 - d);
                    float dm = a - 1.0f;
                    commit += dm * dm;
                    float e4 = 400.0f * a;
                    if (e4 < 40.0f) { lpmax -= log1pf(__expf(-e4)); wts[k] = e4; msk[k] = 1 << (13 - d); k++; }
                }
                const float LCLIP = -11.512925465f;   // log(1e-5)
                const int M = 1 << k;
                for (int m = 0; m < M; m++) {
                    float lp = lpmax; int flip = 0;
                    for (int i = 0; i < k; i++)
                        if ((m >> i) & 1) { lp -= wts[i]; flip |= msk[i]; }
                    float p = __expf(lp);
                    E -= p * fmaxf(lp, LCLIP);
                    atomicAdd(&g_avgp[idx ^ flip], p);
                }
                idxf[t] = (float)idx;
            }
#pragma unroll
            for (int o = 16; o; o >>= 1) {
                E      += __shfl_xor_sync(0xffffffffu, E, o);
                commit += __shfl_xor_sync(0xffffffffu, commit, o);
            }
            if (lane == 0) { atomicAdd(&g_scal[0], E); atomicAdd(&g_scal[1], commit); }
        }
    }
}

// grid=FINBLK x 256: one bin per thread; last-arriving block finishes scalar math.
__global__ void __launch_bounds__(256) lfq_final(float* __restrict__ aux, int ntok)
{
    __shared__ float red[8];
    __shared__ bool amlast;
    const int tid = threadIdx.x;
    const int j = blockIdx.x * 256 + tid;       // FINBLK*256 == CBS
    const float inv_n = 1.0f / (float)ntok;

    float ps_sum = 0.0f, cm_sum = 0.0f;
    if (tid == 0) { ps_sum = __ldcg(&g_scal[0]); cm_sum = __ldcg(&g_scal[1]); }

    float v = __ldcg(&g_avgp[j]);
    g_avgp[j] = 0.0f;                           // reset for next graph replay
    float a = v * inv_n;
    float s = -a * __logf(fmaxf(a, 1e-5f));     // a==0 contributes exactly 0

#pragma unroll
    for (int o = 16; o; o >>= 1) s += __shfl_xor_sync(0xffffffffu, s, o);
    if ((tid & 31) == 0) red[tid >> 5] = s;
    __syncthreads();
    if (tid == 0) {
        float bs = red[0];
#pragma unroll
        for (int w = 1; w < 8; w++) bs += red[w];
        atomicAdd(&g_ent, bs);
        __threadfence();                        // release: ent-add before ctr-add
        unsigned int old = atomicAdd(&g_ctr, 1u);
        amlast = (old == (unsigned)(gridDim.x - 1));
    }
    __syncthreads();
    if (amlast && tid == 0) {
        __threadfence();                        // acquire
        float cbent = *(volatile float*)&g_ent;
        float ps = ps_sum * inv_n;
        float cm = cm_sum * (inv_n / (float)CBD);
        aux[0] = 0.1f * (ps - cbent) + 0.25f * cm;
        g_ent = 0.0f; g_ctr = 0u; g_scal[0] = 0.0f; g_scal[1] = 0.0f;
    }
}

extern "C" void kernel_launch(void* const* d_in, const int* in_sizes, int n_in,
                              void* d_out, int out_size)
{
    const float* x     = (const float*)d_in[0];
    const float* w_in  = (const float*)d_in[1];
    const float* b_in  = (const float*)d_in[2];
    const float* w_out = (const float*)d_in[3];
    const float* b_out = (const float*)d_in[4];

    const int ntok = in_sizes[0] / DIMX;   // 4096

    float* out  = (float*)d_out;
    float* idxf = out + (size_t)ntok * DIMX;
    float* aux  = idxf + ntok;

    cudaFuncSetAttribute(lfq_main, cudaFuncAttributeMaxDynamicSharedMemorySize, SMEM_TOTAL);

    int nblk = (ntok + TPB - 1) / TPB;
    if (nblk > MAXBLK) nblk = MAXBLK;
    lfq_main<<<nblk, NTHR, SMEM_TOTAL>>>(x, w_in, b_in, w_out, b_out, out, idxf, ntok);
    lfq_final<<<FINBLK, 256>>>(aux, ntok);
}